// round 7
// baseline (speedup 1.0000x reference)
#include <cuda_runtime.h>
#include <cuda_bf16.h>
#include <math.h>
#include <stdint.h>

#define NROWS 8192
#define DIM   512

// ---------------------------------------------------------------------------
// Scratch (static device globals — no runtime allocation).
// ---------------------------------------------------------------------------
__device__ float g_Q[NROWS * DIM];
__device__ float g_K[NROWS * DIM];
__device__ float g_V[NROWS * DIM];
__device__ float g_A[NROWS * DIM];

__device__ __nv_bfloat16 g_xhi[NROWS * DIM];
__device__ __nv_bfloat16 g_xlo[NROWS * DIM];
__device__ __nv_bfloat16 g_ahi[NROWS * DIM];
__device__ __nv_bfloat16 g_alo[NROWS * DIM];
__device__ __nv_bfloat16 g_whi[4][DIM * DIM];
__device__ __nv_bfloat16 g_wlo[4][DIM * DIM];

// ---------------------------------------------------------------------------
// Helpers (baseline sm_103 ISA only: ldmatrix / mma.sync / cp.async)
// ---------------------------------------------------------------------------
__device__ __forceinline__ uint32_t smem_to_u32(const void* p) {
    uint32_t a;
    asm("{ .reg .u64 t; cvta.to.shared.u64 t, %1; cvt.u32.u64 %0, t; }" : "=r"(a) : "l"(p));
    return a;
}
__device__ __forceinline__ void cp_async16(uint32_t s, const void* g) {
    asm volatile("cp.async.cg.shared.global [%0], [%1], 16;" :: "r"(s), "l"(g));
}
__device__ __forceinline__ void cp_commit() { asm volatile("cp.async.commit_group;" ::: "memory"); }
__device__ __forceinline__ void cp_wait1()  { asm volatile("cp.async.wait_group 1;" ::: "memory"); }
__device__ __forceinline__ void cp_wait0()  { asm volatile("cp.async.wait_group 0;" ::: "memory"); }

__device__ __forceinline__ void ldsm_x4(uint32_t* r, uint32_t addr) {
    asm volatile("ldmatrix.sync.aligned.m8n8.x4.shared.b16 {%0,%1,%2,%3}, [%4];"
                 : "=r"(r[0]), "=r"(r[1]), "=r"(r[2]), "=r"(r[3]) : "r"(addr));
}
__device__ __forceinline__ void mma16816(float* d, const uint32_t* a, uint32_t b0, uint32_t b1) {
    asm volatile(
        "mma.sync.aligned.m16n8k16.row.col.f32.bf16.bf16.f32 "
        "{%0,%1,%2,%3}, {%4,%5,%6,%7}, {%8,%9}, {%0,%1,%2,%3};"
        : "+f"(d[0]), "+f"(d[1]), "+f"(d[2]), "+f"(d[3])
        : "r"(a[0]), "r"(a[1]), "r"(a[2]), "r"(a[3]), "r"(b0), "r"(b1));
}

// ---------------------------------------------------------------------------
// fp32 -> bf16 hi/lo split (elementwise)
// ---------------------------------------------------------------------------
__global__ __launch_bounds__(256) void split_kernel(
    const float* __restrict__ x, __nv_bfloat16* __restrict__ hi,
    __nv_bfloat16* __restrict__ lo, int n)
{
    int i = blockIdx.x * 256 + threadIdx.x;
    if (i < n) {
        float v = x[i];
        __nv_bfloat16 h = __float2bfloat16_rn(v);
        float r = v - __bfloat162float(h);
        hi[i] = h;
        lo[i] = __float2bfloat16_rn(r);
    }
}

// ---------------------------------------------------------------------------
// W [K=512][N=512] row-major -> transposed bf16 hi/lo [N][K]
// ---------------------------------------------------------------------------
__global__ __launch_bounds__(256) void wsplit_t_kernel(
    const float* __restrict__ W, __nv_bfloat16* __restrict__ hi, __nv_bfloat16* __restrict__ lo)
{
    __shared__ float t[32][33];
    const int tx = threadIdx.x & 31;
    const int ty = threadIdx.x >> 5;
    const int k0 = blockIdx.y * 32;
    const int n0 = blockIdx.x * 32;
#pragma unroll
    for (int i = 0; i < 32; i += 8)
        t[ty + i][tx] = W[(size_t)(k0 + ty + i) * 512 + n0 + tx];
    __syncthreads();
#pragma unroll
    for (int i = 0; i < 32; i += 8) {
        float v = t[tx][ty + i];
        __nv_bfloat16 h = __float2bfloat16_rn(v);
        float r = v - __bfloat162float(h);
        size_t idx = (size_t)(n0 + ty + i) * 512 + k0 + tx;
        hi[idx] = h;
        lo[idx] = __float2bfloat16_rn(r);
    }
}

// ---------------------------------------------------------------------------
// HMMA GEMM (unchanged from R5 passing version)
// ---------------------------------------------------------------------------
static constexpr int TILE_BYTES = 128 * 144;
static constexpr int STAGE_B    = 4 * TILE_BYTES;
static constexpr int GEMM_SMEM_TOTAL = 2 * STAGE_B;

__device__ __forceinline__ void load_tile(
    uint32_t sdst, const __nv_bfloat16* __restrict__ src, int rowbase, int kc, int tid)
{
    const char* s = (const char*)(src + (size_t)rowbase * 512) + kc * 128;
#pragma unroll
    for (int i = 0; i < 4; i++) {
        int f   = tid + i * 256;
        int row = f >> 3;
        int c   = f & 7;
        cp_async16(sdst + row * 144 + c * 16, s + (size_t)row * 1024 + c * 16);
    }
}

__global__ __launch_bounds__(256)
void gemm_mma_kernel(const __nv_bfloat16* __restrict__ Ahi, const __nv_bfloat16* __restrict__ Alo,
                     const __nv_bfloat16* __restrict__ Bhi, const __nv_bfloat16* __restrict__ Blo,
                     const float* __restrict__ bias, float* __restrict__ C)
{
    extern __shared__ char smem_c[];
    const uint32_t sb = smem_to_u32(smem_c);

    const int tid  = threadIdx.x;
    const int wid  = tid >> 5;
    const int lane = tid & 31;
    const int m0 = blockIdx.y * 128;
    const int n0 = blockIdx.x * 128;
    const int wm = (wid & 1) * 64;
    const int wn = (wid >> 1) * 32;

    float acc[4][4][4];
#pragma unroll
    for (int im = 0; im < 4; im++)
#pragma unroll
        for (int in = 0; in < 4; in++)
#pragma unroll
            for (int e = 0; e < 4; e++) acc[im][in][e] = 0.f;

    {
        uint32_t st = sb;
        load_tile(st + 0 * TILE_BYTES, Ahi, m0, 0, tid);
        load_tile(st + 1 * TILE_BYTES, Alo, m0, 0, tid);
        load_tile(st + 2 * TILE_BYTES, Bhi, n0, 0, tid);
        load_tile(st + 3 * TILE_BYTES, Blo, n0, 0, tid);
        cp_commit();
    }

    const int rowA  = wm + (lane & 15);
    const int rowB  = wn + (lane & 15);
    const int khalf = (lane >> 4) * 8;

    for (int kc = 0; kc < 8; kc++) {
        const uint32_t cur = sb + (uint32_t)(kc & 1) * STAGE_B;
        if (kc < 7) {
            uint32_t nxt = sb + (uint32_t)((kc + 1) & 1) * STAGE_B;
            load_tile(nxt + 0 * TILE_BYTES, Ahi, m0, kc + 1, tid);
            load_tile(nxt + 1 * TILE_BYTES, Alo, m0, kc + 1, tid);
            load_tile(nxt + 2 * TILE_BYTES, Bhi, n0, kc + 1, tid);
            load_tile(nxt + 3 * TILE_BYTES, Blo, n0, kc + 1, tid);
            cp_commit();
            cp_wait1();
        } else {
            cp_wait0();
        }
        __syncthreads();

        const uint32_t sAh = cur + 0 * TILE_BYTES;
        const uint32_t sAl = cur + 1 * TILE_BYTES;
        const uint32_t sBh = cur + 2 * TILE_BYTES;
        const uint32_t sBl = cur + 3 * TILE_BYTES;

#pragma unroll
        for (int ks = 0; ks < 4; ks++) {
            const int ke = ks * 16 + khalf;
            uint32_t ah[4][4], al[4][4], bh[2][4], bl[2][4];
#pragma unroll
            for (int im = 0; im < 4; im++) {
                ldsm_x4(ah[im], sAh + ((rowA + im * 16) * 72 + ke) * 2);
                ldsm_x4(al[im], sAl + ((rowA + im * 16) * 72 + ke) * 2);
            }
#pragma unroll
            for (int ib = 0; ib < 2; ib++) {
                ldsm_x4(bh[ib], sBh + ((rowB + ib * 16) * 72 + ke) * 2);
                ldsm_x4(bl[ib], sBl + ((rowB + ib * 16) * 72 + ke) * 2);
            }
#pragma unroll
            for (int im = 0; im < 4; im++) {
#pragma unroll
                for (int in = 0; in < 4; in++) {
                    const int ib  = in >> 1;
                    const int sel = in & 1;
                    mma16816(acc[im][in], ah[im], bh[ib][sel], bh[ib][sel + 2]);
                    mma16816(acc[im][in], ah[im], bl[ib][sel], bl[ib][sel + 2]);
                    mma16816(acc[im][in], al[im], bh[ib][sel], bh[ib][sel + 2]);
                }
            }
        }
        __syncthreads();
    }

    const int gid = lane >> 2;
    const int tg  = lane & 3;
#pragma unroll
    for (int im = 0; im < 4; im++) {
        const int r0 = m0 + wm + im * 16 + gid;
        const int r1 = r0 + 8;
#pragma unroll
        for (int in = 0; in < 4; in++) {
            const int col = n0 + wn + in * 8 + tg * 2;
            const float b0 = bias[col], b1 = bias[col + 1];
            float2 v0 = make_float2(acc[im][in][0] + b0, acc[im][in][1] + b1);
            float2 v1 = make_float2(acc[im][in][2] + b0, acc[im][in][3] + b1);
            *(float2*)(C + (size_t)r0 * 512 + col) = v0;
            *(float2*)(C + (size_t)r1 * 512 + col) = v1;
        }
    }
}

// ---------------------------------------------------------------------------
// Group-tiled attention.
// Grid: (64 groups, 8 query-tiles of 32). 256 threads (8 warps).
// Lane mapping: lane = qq*8 + slice, q_local = warp*4 + qq.
// Thread owns query q_local's dims at float4 indices slice + 8*i (i=0..15).
// K/V streamed via 32-row smem chunks; block-wise online softmax.
// Deterministic: row lists built in ascending order; fixed reduction trees.
// ---------------------------------------------------------------------------
static constexpr int ATT_META   = 4096;                   // cnt(1K) pre(1K) list(2K)
static constexpr int ATT_KBYTES = 32 * 512 * 4;           // 64 KB
static constexpr int ATT_SMEM_TOTAL = ATT_META + 2 * ATT_KBYTES;  // 135168

__global__ __launch_bounds__(256) void attn_group_kernel(
    const float* __restrict__ Q, const float* __restrict__ K,
    const float* __restrict__ V, const int* __restrict__ labels,
    float* __restrict__ Aout)
{
    extern __shared__ char sm_raw[];
    int*    s_cnt  = (int*)sm_raw;                // 256
    int*    s_pre  = (int*)(sm_raw + 1024);       // 256
    int*    s_list = (int*)(sm_raw + 2048);       // 512
    float4* sK4    = (float4*)(sm_raw + ATT_META);
    float4* sV4    = (float4*)(sm_raw + ATT_META + ATT_KBYTES);

    const int g    = blockIdx.x;
    const int qt   = blockIdx.y;
    const int tid  = threadIdx.x;
    const int warp = tid >> 5;
    const int lane = tid & 31;
    const int qq    = lane >> 3;      // 0..3
    const int slice = lane & 7;       // 0..7
    const int q_local = warp * 4 + qq;  // 0..31

    // --- per-chunk match counts ---
    for (int c = warp; c < 256; c += 8) {
        int lab = labels[c * 32 + lane];
        unsigned m = __ballot_sync(0xffffffffu, lab == g);
        if (lane == 0) s_cnt[c] = __popc(m);
    }
    __syncthreads();

    // --- exclusive prefix over 256 counts (warp 0) ---
    if (warp == 0) {
        int vals[8];
        int run = 0;
#pragma unroll
        for (int j = 0; j < 8; j++) {
            int t = s_cnt[lane * 8 + j];
            vals[j] = run;
            run += t;
        }
        int x = run;
#pragma unroll
        for (int off = 1; off < 32; off <<= 1) {
            int y = __shfl_up_sync(0xffffffffu, x, off);
            if (lane >= off) x += y;
        }
        int excl = x - run;
#pragma unroll
        for (int j = 0; j < 8; j++) s_pre[lane * 8 + j] = excl + vals[j];
    }
    __syncthreads();

    const int n = s_pre[255] + s_cnt[255];
    if (qt * 32 >= n) return;

    // --- fill row list (ascending) ---
    for (int c = warp; c < 256; c += 8) {
        int lab = labels[c * 32 + lane];
        unsigned m = __ballot_sync(0xffffffffu, lab == g);
        if (lab == g) {
            int idx = s_pre[c] + __popc(m & ((1u << lane) - 1));
            if (idx < 512) s_list[idx] = c * 32 + lane;
        }
    }
    __syncthreads();

    const int nq   = min(32, n - qt * 32);
    const int myq  = qt * 32 + q_local;
    const int rowq = s_list[min(myq, n - 1)];

    const float4* Q4 = (const float4*)Q;
    const float4* K4 = (const float4*)K;
    const float4* V4 = (const float4*)V;

    // Q row into registers (interleaved float4 ownership)
    float4 qreg[16];
#pragma unroll
    for (int i = 0; i < 16; i++)
        qreg[i] = Q4[(size_t)rowq * 128 + slice + 8 * i];

    float4 acc[16];
#pragma unroll
    for (int i = 0; i < 16; i++) acc[i] = make_float4(0.f, 0.f, 0.f, 0.f);
    float m_ = -INFINITY, l_ = 0.f;

    const float scale = 0.04419417382415922f;  // 1/sqrt(512)

    for (int k0 = 0; k0 < n; k0 += 32) {
        const int nk = min(32, n - k0);
        __syncthreads();
        // load K/V chunk (zero-pad missing rows)
#pragma unroll
        for (int it = 0; it < 16; it++) {
            int f   = tid + it * 256;
            int row = f >> 7;
            int j   = f & 127;
            if (row < nk) {
                int r = s_list[k0 + row];
                sK4[row * 128 + j] = K4[(size_t)r * 128 + j];
                sV4[row * 128 + j] = V4[(size_t)r * 128 + j];
            } else {
                sK4[row * 128 + j] = make_float4(0.f, 0.f, 0.f, 0.f);
                sV4[row * 128 + j] = make_float4(0.f, 0.f, 0.f, 0.f);
            }
        }
        __syncthreads();

        // scores: partial dot over this thread's 64 dims
        float s[32];
#pragma unroll
        for (int k = 0; k < 32; k++) {
            float p0 = 0.f, p1 = 0.f;
            const float4* kr = sK4 + k * 128 + slice;
#pragma unroll
            for (int i = 0; i < 16; i += 2) {
                float4 a = qreg[i],     b = kr[8 * i];
                float4 c = qreg[i + 1], d = kr[8 * (i + 1)];
                p0 = fmaf(a.x, b.x, p0); p0 = fmaf(a.y, b.y, p0);
                p0 = fmaf(a.z, b.z, p0); p0 = fmaf(a.w, b.w, p0);
                p1 = fmaf(c.x, d.x, p1); p1 = fmaf(c.y, d.y, p1);
                p1 = fmaf(c.z, d.z, p1); p1 = fmaf(c.w, d.w, p1);
            }
            s[k] = p0 + p1;
        }
        // reduce across the 8 slice-lanes (butterfly, fixed order)
#pragma unroll
        for (int k = 0; k < 32; k++) {
            float v = s[k];
            v += __shfl_xor_sync(0xffffffffu, v, 1);
            v += __shfl_xor_sync(0xffffffffu, v, 2);
            v += __shfl_xor_sync(0xffffffffu, v, 4);
            s[k] = v;
        }

        // mask + block max
        float cmax = -INFINITY;
#pragma unroll
        for (int k = 0; k < 32; k++) {
            s[k] = (k < nk) ? s[k] * scale : -INFINITY;
            cmax = fmaxf(cmax, s[k]);
        }
        const float mnew = fmaxf(m_, cmax);
        const float corr = __expf(m_ - mnew);
        float psum = 0.f;
#pragma unroll
        for (int k = 0; k < 32; k++) {
            s[k] = __expf(s[k] - mnew);   // 0 for masked
            psum += s[k];
        }
        l_ = l_ * corr + psum;
        m_ = mnew;
#pragma unroll
        for (int i = 0; i < 16; i++) {
            acc[i].x *= corr; acc[i].y *= corr; acc[i].z *= corr; acc[i].w *= corr;
        }
        // accumulate P @ V (padded rows are zero-filled -> exact 0 contribution)
#pragma unroll
        for (int k = 0; k < 32; k++) {
            const float p = s[k];
            const float4* vr = sV4 + k * 128 + slice;
#pragma unroll
            for (int i = 0; i < 16; i++) {
                float4 v = vr[8 * i];
                acc[i].x = fmaf(p, v.x, acc[i].x);
                acc[i].y = fmaf(p, v.y, acc[i].y);
                acc[i].z = fmaf(p, v.z, acc[i].z);
                acc[i].w = fmaf(p, v.w, acc[i].w);
            }
        }
    }

    if (q_local < nq) {
        const float invl = 1.0f / l_;
        float4* dst = (float4*)(Aout + (size_t)rowq * 512);
#pragma unroll
        for (int i = 0; i < 16; i++) {
            float4 o = acc[i];
            o.x *= invl; o.y *= invl; o.z *= invl; o.w *= invl;
            dst[slice + 8 * i] = o;
        }
    }
}

// ---------------------------------------------------------------------------
// Zero rows with label == -1 (reference: invalid rows -> zeros before Wo)
// ---------------------------------------------------------------------------
__global__ __launch_bounds__(128) void zero_invalid_kernel(
    const int* __restrict__ labels, float* __restrict__ A)
{
    const int row = blockIdx.x;
    if (labels[row] >= 0) return;
    ((float4*)(A + (size_t)row * 512))[threadIdx.x] = make_float4(0.f, 0.f, 0.f, 0.f);
}

// ---------------------------------------------------------------------------
extern "C" void kernel_launch(void* const* d_in, const int* in_sizes, int n_in,
                              void* d_out, int out_size)
{
    const float* x      = (const float*)d_in[0];
    const int*   labels = (const int*)  d_in[1];
    const float* Wq     = (const float*)d_in[2];
    const float* bq     = (const float*)d_in[3];
    const float* Wk     = (const float*)d_in[4];
    const float* bk     = (const float*)d_in[5];
    const float* Wv     = (const float*)d_in[6];
    const float* bv     = (const float*)d_in[7];
    const float* Wo     = (const float*)d_in[8];
    const float* bo     = (const float*)d_in[9];
    float* out = (float*)d_out;

    float *Qp, *Kp, *Vp, *Ap;
    cudaGetSymbolAddress((void**)&Qp, g_Q);
    cudaGetSymbolAddress((void**)&Kp, g_K);
    cudaGetSymbolAddress((void**)&Vp, g_V);
    cudaGetSymbolAddress((void**)&Ap, g_A);
    __nv_bfloat16 *xhi, *xlo, *ahi, *alo, *whi, *wlo;
    cudaGetSymbolAddress((void**)&xhi, g_xhi);
    cudaGetSymbolAddress((void**)&xlo, g_xlo);
    cudaGetSymbolAddress((void**)&ahi, g_ahi);
    cudaGetSymbolAddress((void**)&alo, g_alo);
    cudaGetSymbolAddress((void**)&whi, g_whi);
    cudaGetSymbolAddress((void**)&wlo, g_wlo);

    cudaFuncSetAttribute(gemm_mma_kernel, cudaFuncAttributeMaxDynamicSharedMemorySize,
                         GEMM_SMEM_TOTAL);
    cudaFuncSetAttribute(attn_group_kernel, cudaFuncAttributeMaxDynamicSharedMemorySize,
                         ATT_SMEM_TOTAL);

    const int nelem = NROWS * DIM;
    split_kernel<<<(nelem + 255) / 256, 256>>>(x, xhi, xlo, nelem);

    dim3 wgrid(16, 16);
    wsplit_t_kernel<<<wgrid, 256>>>(Wq, whi + 0 * DIM * DIM, wlo + 0 * DIM * DIM);
    wsplit_t_kernel<<<wgrid, 256>>>(Wk, whi + 1 * DIM * DIM, wlo + 1 * DIM * DIM);
    wsplit_t_kernel<<<wgrid, 256>>>(Wv, whi + 2 * DIM * DIM, wlo + 2 * DIM * DIM);
    wsplit_t_kernel<<<wgrid, 256>>>(Wo, whi + 3 * DIM * DIM, wlo + 3 * DIM * DIM);

    dim3 ggrid(DIM / 128, NROWS / 128);   // (4, 64)
    gemm_mma_kernel<<<ggrid, 256, GEMM_SMEM_TOTAL>>>(xhi, xlo, whi + 0 * DIM * DIM, wlo + 0 * DIM * DIM, bq, Qp);
    gemm_mma_kernel<<<ggrid, 256, GEMM_SMEM_TOTAL>>>(xhi, xlo, whi + 1 * DIM * DIM, wlo + 1 * DIM * DIM, bk, Kp);
    gemm_mma_kernel<<<ggrid, 256, GEMM_SMEM_TOTAL>>>(xhi, xlo, whi + 2 * DIM * DIM, wlo + 2 * DIM * DIM, bv, Vp);

    dim3 agrid(64, 8);
    attn_group_kernel<<<agrid, 256, ATT_SMEM_TOTAL>>>(Qp, Kp, Vp, labels, Ap);
    zero_invalid_kernel<<<NROWS, 128>>>(labels, Ap);

    split_kernel<<<(nelem + 255) / 256, 256>>>(Ap, ahi, alo, nelem);
    gemm_mma_kernel<<<ggrid, 256, GEMM_SMEM_TOTAL>>>(ahi, alo, whi + 3 * DIM * DIM, wlo + 3 * DIM * DIM, bo, out);
}

// round 10
// speedup vs baseline: 1.1644x; 1.1644x over previous
#include <cuda_runtime.h>
#include <cuda_bf16.h>
#include <math.h>
#include <stdint.h>

#define NROWS 8192
#define DIM   512
#define NG    64
#define CAP   256          // per-group row capacity (n_g ~126 +/- 11; 256 is >11 sigma)

// ---------------------------------------------------------------------------
// Scratch (static device globals — no runtime allocation; zero-initialized).
// ---------------------------------------------------------------------------
__device__ float g_Q[NROWS * DIM];
__device__ float g_K[NROWS * DIM];
__device__ float g_V[NROWS * DIM];
__device__ float g_A[NROWS * DIM];

__device__ __nv_bfloat16 g_xhi[NROWS * DIM];
__device__ __nv_bfloat16 g_xlo[NROWS * DIM];
__device__ __nv_bfloat16 g_ahi[NROWS * DIM];   // reused: Q hi, then A hi
__device__ __nv_bfloat16 g_alo[NROWS * DIM];
__device__ __nv_bfloat16 g_khi[NROWS * DIM];
__device__ __nv_bfloat16 g_klo[NROWS * DIM];
__device__ __nv_bfloat16 g_whi[4][DIM * DIM];
__device__ __nv_bfloat16 g_wlo[4][DIM * DIM];

// attention staging
__device__ int   g_list[NG][CAP];
__device__ int   g_cnt[NG];
__device__ float g_S  [NG][CAP * CAP];             // scores fp32
__device__ __nv_bfloat16 g_Phi[NG][CAP * CAP];     // softmax probs hi/lo
__device__ __nv_bfloat16 g_Plo[NG][CAP * CAP];
__device__ __nv_bfloat16 g_VThi[NG][DIM * CAP];    // V^T gathered [dim][key]
__device__ __nv_bfloat16 g_VTlo[NG][DIM * CAP];

// ---------------------------------------------------------------------------
// Helpers (baseline sm_103 ISA only)
// ---------------------------------------------------------------------------
__device__ __forceinline__ uint32_t smem_to_u32(const void* p) {
    uint32_t a;
    asm("{ .reg .u64 t; cvta.to.shared.u64 t, %1; cvt.u32.u64 %0, t; }" : "=r"(a) : "l"(p));
    return a;
}
__device__ __forceinline__ void cp_async16(uint32_t s, const void* g) {
    asm volatile("cp.async.cg.shared.global [%0], [%1], 16;" :: "r"(s), "l"(g));
}
__device__ __forceinline__ void cp_commit() { asm volatile("cp.async.commit_group;" ::: "memory"); }
__device__ __forceinline__ void cp_wait1()  { asm volatile("cp.async.wait_group 1;" ::: "memory"); }
__device__ __forceinline__ void cp_wait0()  { asm volatile("cp.async.wait_group 0;" ::: "memory"); }

__device__ __forceinline__ void ldsm_x4(uint32_t* r, uint32_t addr) {
    asm volatile("ldmatrix.sync.aligned.m8n8.x4.shared.b16 {%0,%1,%2,%3}, [%4];"
                 : "=r"(r[0]), "=r"(r[1]), "=r"(r[2]), "=r"(r[3]) : "r"(addr));
}
__device__ __forceinline__ void mma16816(float* d, const uint32_t* a, uint32_t b0, uint32_t b1) {
    asm volatile(
        "mma.sync.aligned.m16n8k16.row.col.f32.bf16.bf16.f32 "
        "{%0,%1,%2,%3}, {%4,%5,%6,%7}, {%8,%9}, {%0,%1,%2,%3};"
        : "+f"(d[0]), "+f"(d[1]), "+f"(d[2]), "+f"(d[3])
        : "r"(a[0]), "r"(a[1]), "r"(a[2]), "r"(a[3]), "r"(b0), "r"(b1));
}

// ---------------------------------------------------------------------------
// fp32 -> bf16 hi/lo split (elementwise)
// ---------------------------------------------------------------------------
__global__ __launch_bounds__(256) void split_kernel(
    const float* __restrict__ x, __nv_bfloat16* __restrict__ hi,
    __nv_bfloat16* __restrict__ lo, int n)
{
    int i = blockIdx.x * 256 + threadIdx.x;
    if (i < n) {
        float v = x[i];
        __nv_bfloat16 h = __float2bfloat16_rn(v);
        float r = v - __bfloat162float(h);
        hi[i] = h;
        lo[i] = __float2bfloat16_rn(r);
    }
}

// ---------------------------------------------------------------------------
// W [K][N] row-major -> transposed bf16 hi/lo [N][K]
// ---------------------------------------------------------------------------
__global__ __launch_bounds__(256) void wsplit_t_kernel(
    const float* __restrict__ W, __nv_bfloat16* __restrict__ hi, __nv_bfloat16* __restrict__ lo)
{
    __shared__ float t[32][33];
    const int tx = threadIdx.x & 31;
    const int ty = threadIdx.x >> 5;
    const int k0 = blockIdx.y * 32;
    const int n0 = blockIdx.x * 32;
#pragma unroll
    for (int i = 0; i < 32; i += 8)
        t[ty + i][tx] = W[(size_t)(k0 + ty + i) * 512 + n0 + tx];
    __syncthreads();
#pragma unroll
    for (int i = 0; i < 32; i += 8) {
        float v = t[tx][ty + i];
        __nv_bfloat16 h = __float2bfloat16_rn(v);
        float r = v - __bfloat162float(h);
        size_t idx = (size_t)(n0 + ty + i) * 512 + k0 + tx;
        hi[idx] = h;
        lo[idx] = __float2bfloat16_rn(r);
    }
}

// ---------------------------------------------------------------------------
// Shared HMMA core pieces
// ---------------------------------------------------------------------------
static constexpr int TILE_BYTES = 128 * 144;
static constexpr int STAGE_B    = 4 * TILE_BYTES;
static constexpr int GEMM_SMEM_TOTAL = 2 * STAGE_B;   // 147456

// direct load: src row-major, stride_b bytes/row, 128 rows x 64 bf16 cols
__device__ __forceinline__ void load_tile2(
    uint32_t sdst, const char* src, size_t stride_b, int rowbase, int kc, int tid)
{
#pragma unroll
    for (int i = 0; i < 4; i++) {
        int f   = tid + i * 256;
        int row = f >> 3;
        int c   = f & 7;
        cp_async16(sdst + row * 144 + c * 16,
                   src + (size_t)(rowbase + row) * stride_b + (size_t)kc * 128 + c * 16);
    }
}
// indirect load: per-row global index from smem list (stride fixed 1024B = 512 bf16)
__device__ __forceinline__ void load_tile_idx(
    uint32_t sdst, const char* src, const int* rows, int kc, int tid)
{
#pragma unroll
    for (int i = 0; i < 4; i++) {
        int f   = tid + i * 256;
        int row = f >> 3;
        int c   = f & 7;
        cp_async16(sdst + row * 144 + c * 16,
                   src + (size_t)rows[row] * 1024 + (size_t)kc * 128 + c * 16);
    }
}

// one K=64 chunk of the 3-term hi/lo mma (Ah*Bh + Ah*Bl + Al*Bh)
__device__ __forceinline__ void mma_chunk(
    uint32_t cur, int rowA, int rowB, int khalf, float acc[4][4][4])
{
    const uint32_t sAh = cur + 0 * TILE_BYTES;
    const uint32_t sAl = cur + 1 * TILE_BYTES;
    const uint32_t sBh = cur + 2 * TILE_BYTES;
    const uint32_t sBl = cur + 3 * TILE_BYTES;
#pragma unroll
    for (int ks = 0; ks < 4; ks++) {
        const int ke = ks * 16 + khalf;
        uint32_t ah[4][4], al[4][4], bh[2][4], bl[2][4];
#pragma unroll
        for (int im = 0; im < 4; im++) {
            ldsm_x4(ah[im], sAh + ((rowA + im * 16) * 72 + ke) * 2);
            ldsm_x4(al[im], sAl + ((rowA + im * 16) * 72 + ke) * 2);
        }
#pragma unroll
        for (int ib = 0; ib < 2; ib++) {
            ldsm_x4(bh[ib], sBh + ((rowB + ib * 16) * 72 + ke) * 2);
            ldsm_x4(bl[ib], sBl + ((rowB + ib * 16) * 72 + ke) * 2);
        }
#pragma unroll
        for (int im = 0; im < 4; im++) {
#pragma unroll
            for (int in = 0; in < 4; in++) {
                const int ib  = in >> 1;
                const int sel = in & 1;
                mma16816(acc[im][in], ah[im], bh[ib][sel], bh[ib][sel + 2]);
                mma16816(acc[im][in], ah[im], bl[ib][sel], bl[ib][sel + 2]);
                mma16816(acc[im][in], al[im], bh[ib][sel], bh[ib][sel + 2]);
            }
        }
    }
}

// ---------------------------------------------------------------------------
// Dense GEMM with bias (projections + output): C = (Ahi+Alo) @ (Bhi+Blo)^T + b
// ---------------------------------------------------------------------------
__global__ __launch_bounds__(256)
void gemm_mma_kernel(const __nv_bfloat16* __restrict__ Ahi, const __nv_bfloat16* __restrict__ Alo,
                     const __nv_bfloat16* __restrict__ Bhi, const __nv_bfloat16* __restrict__ Blo,
                     const float* __restrict__ bias, float* __restrict__ C)
{
    extern __shared__ char smem_c[];
    const uint32_t sb = smem_to_u32(smem_c);
    const int tid  = threadIdx.x;
    const int wid  = tid >> 5;
    const int lane = tid & 31;
    const int m0 = blockIdx.y * 128;
    const int n0 = blockIdx.x * 128;
    const int wm = (wid & 1) * 64;
    const int wn = (wid >> 1) * 32;

    float acc[4][4][4];
#pragma unroll
    for (int im = 0; im < 4; im++)
#pragma unroll
        for (int in = 0; in < 4; in++)
#pragma unroll
            for (int e = 0; e < 4; e++) acc[im][in][e] = 0.f;

    load_tile2(sb + 0 * TILE_BYTES, (const char*)Ahi, 1024, m0, 0, tid);
    load_tile2(sb + 1 * TILE_BYTES, (const char*)Alo, 1024, m0, 0, tid);
    load_tile2(sb + 2 * TILE_BYTES, (const char*)Bhi, 1024, n0, 0, tid);
    load_tile2(sb + 3 * TILE_BYTES, (const char*)Blo, 1024, n0, 0, tid);
    cp_commit();

    const int rowA  = wm + (lane & 15);
    const int rowB  = wn + (lane & 15);
    const int khalf = (lane >> 4) * 8;

    for (int kc = 0; kc < 8; kc++) {
        const uint32_t cur = sb + (uint32_t)(kc & 1) * STAGE_B;
        if (kc < 7) {
            uint32_t nxt = sb + (uint32_t)((kc + 1) & 1) * STAGE_B;
            load_tile2(nxt + 0 * TILE_BYTES, (const char*)Ahi, 1024, m0, kc + 1, tid);
            load_tile2(nxt + 1 * TILE_BYTES, (const char*)Alo, 1024, m0, kc + 1, tid);
            load_tile2(nxt + 2 * TILE_BYTES, (const char*)Bhi, 1024, n0, kc + 1, tid);
            load_tile2(nxt + 3 * TILE_BYTES, (const char*)Blo, 1024, n0, kc + 1, tid);
            cp_commit();
            cp_wait1();
        } else {
            cp_wait0();
        }
        __syncthreads();
        mma_chunk(cur, rowA, rowB, khalf, acc);
        __syncthreads();
    }

    const int gid = lane >> 2;
    const int tg  = lane & 3;
#pragma unroll
    for (int im = 0; im < 4; im++) {
        const int r0 = m0 + wm + im * 16 + gid;
        const int r1 = r0 + 8;
#pragma unroll
        for (int in = 0; in < 4; in++) {
            const int col = n0 + wn + in * 8 + tg * 2;
            const float b0 = bias[col], b1 = bias[col + 1];
            *(float2*)(C + (size_t)r0 * 512 + col) = make_float2(acc[im][in][0] + b0, acc[im][in][1] + b1);
            *(float2*)(C + (size_t)r1 * 512 + col) = make_float2(acc[im][in][2] + b0, acc[im][in][3] + b1);
        }
    }
}

// ---------------------------------------------------------------------------
// Build per-group row lists (deterministic, ascending). Grid = 64 CTAs.
// ---------------------------------------------------------------------------
__global__ __launch_bounds__(256) void build_lists_kernel(const int* __restrict__ labels)
{
    __shared__ int s_cnt[256], s_pre[256], s_list[512];
    const int g    = blockIdx.x;
    const int tid  = threadIdx.x;
    const int warp = tid >> 5;
    const int lane = tid & 31;

    for (int c = warp; c < 256; c += 8) {
        int lab = labels[c * 32 + lane];
        unsigned m = __ballot_sync(0xffffffffu, lab == g);
        if (lane == 0) s_cnt[c] = __popc(m);
    }
    __syncthreads();
    if (warp == 0) {
        int vals[8];
        int run = 0;
#pragma unroll
        for (int j = 0; j < 8; j++) { int t = s_cnt[lane * 8 + j]; vals[j] = run; run += t; }
        int x = run;
#pragma unroll
        for (int off = 1; off < 32; off <<= 1) {
            int y = __shfl_up_sync(0xffffffffu, x, off);
            if (lane >= off) x += y;
        }
        int excl = x - run;
#pragma unroll
        for (int j = 0; j < 8; j++) s_pre[lane * 8 + j] = excl + vals[j];
    }
    __syncthreads();
    const int n = s_pre[255] + s_cnt[255];
    for (int c = warp; c < 256; c += 8) {
        int lab = labels[c * 32 + lane];
        unsigned m = __ballot_sync(0xffffffffu, lab == g);
        if (lab == g) {
            int idx = s_pre[c] + __popc(m & ((1u << lane) - 1));
            if (idx < 512) s_list[idx] = c * 32 + lane;
        }
    }
    __syncthreads();
    if (tid < CAP) g_list[g][tid] = (tid < n) ? s_list[tid] : 0;
    if (tid == 0) g_cnt[g] = (n > CAP) ? CAP : n;
}

// ---------------------------------------------------------------------------
// Gather + transpose + split V: VT[g][dim][key] bf16 hi/lo. Grid (64, 8).
// ---------------------------------------------------------------------------
__global__ __launch_bounds__(256) void vt_build_kernel(const float* __restrict__ V)
{
    const int g  = blockIdx.x;
    const int kt = blockIdx.y;           // key tile of 32
    const int n  = g_cnt[g];
    if (kt * 32 >= n) return;

    __shared__ float t[32][33];
    __shared__ int rows[32];
    const int tx = threadIdx.x & 31;
    const int ty = threadIdx.x >> 5;     // 0..7
    if (threadIdx.x < 32) {
        int key = kt * 32 + threadIdx.x;
        rows[threadIdx.x] = (key < n) ? g_list[g][key] : -1;
    }
    __syncthreads();

    for (int db = 0; db < 16; db++) {
#pragma unroll
        for (int i = 0; i < 32; i += 8) {
            int r = rows[ty + i];
            t[ty + i][tx] = (r >= 0) ? V[(size_t)r * 512 + db * 32 + tx] : 0.f;
        }
        __syncthreads();
#pragma unroll
        for (int i = 0; i < 32; i += 8) {
            int d = db * 32 + ty + i;
            int k = kt * 32 + tx;
            if (k < n) {
                float v = t[tx][ty + i];
                __nv_bfloat16 h = __float2bfloat16_rn(v);
                float r = v - __bfloat162float(h);
                g_VThi[g][d * CAP + k] = h;
                g_VTlo[g][d * CAP + k] = __float2bfloat16_rn(r);
            }
        }
        __syncthreads();
    }
}

// ---------------------------------------------------------------------------
// Scores GEMM: S_g = Q_g @ K_g^T (indirect rows, 3-term hi/lo). Grid (64,2,2).
// ---------------------------------------------------------------------------
__global__ __launch_bounds__(256)
void scores_mma_kernel(const __nv_bfloat16* __restrict__ Qhi, const __nv_bfloat16* __restrict__ Qlo,
                       const __nv_bfloat16* __restrict__ Khi, const __nv_bfloat16* __restrict__ Klo)
{
    const int g  = blockIdx.x;
    const int n  = g_cnt[g];
    const int n0 = blockIdx.y * 128;
    const int m0 = blockIdx.z * 128;
    if (m0 >= n || n0 >= n) return;

    extern __shared__ char smem_c[];
    __shared__ int rA[128], rB[128];
    const uint32_t sb = smem_to_u32(smem_c);
    const int tid  = threadIdx.x;
    const int wid  = tid >> 5;
    const int lane = tid & 31;
    const int wm = (wid & 1) * 64;
    const int wn = (wid >> 1) * 32;

    if (tid < 128) rA[tid] = g_list[g][m0 + tid];
    else           rB[tid - 128] = g_list[g][n0 + tid - 128];
    __syncthreads();

    float acc[4][4][4];
#pragma unroll
    for (int im = 0; im < 4; im++)
#pragma unroll
        for (int in = 0; in < 4; in++)
#pragma unroll
            for (int e = 0; e < 4; e++) acc[im][in][e] = 0.f;

    load_tile_idx(sb + 0 * TILE_BYTES, (const char*)Qhi, rA, 0, tid);
    load_tile_idx(sb + 1 * TILE_BYTES, (const char*)Qlo, rA, 0, tid);
    load_tile_idx(sb + 2 * TILE_BYTES, (const char*)Khi, rB, 0, tid);
    load_tile_idx(sb + 3 * TILE_BYTES, (const char*)Klo, rB, 0, tid);
    cp_commit();

    const int rowA  = wm + (lane & 15);
    const int rowB  = wn + (lane & 15);
    const int khalf = (lane >> 4) * 8;

    for (int kc = 0; kc < 8; kc++) {
        const uint32_t cur = sb + (uint32_t)(kc & 1) * STAGE_B;
        if (kc < 7) {
            uint32_t nxt = sb + (uint32_t)((kc + 1) & 1) * STAGE_B;
            load_tile_idx(nxt + 0 * TILE_BYTES, (const char*)Qhi, rA, kc + 1, tid);
            load_tile_idx(nxt + 1 * TILE_BYTES, (const char*)Qlo, rA, kc + 1, tid);
            load_tile_idx(nxt + 2 * TILE_BYTES, (const char*)Khi, rB, kc + 1, tid);
            load_tile_idx(nxt + 3 * TILE_BYTES, (const char*)Klo, rB, kc + 1, tid);
            cp_commit();
            cp_wait1();
        } else {
            cp_wait0();
        }
        __syncthreads();
        mma_chunk(cur, rowA, rowB, khalf, acc);
        __syncthreads();
    }

    float* S = g_S[g];
    const int gid = lane >> 2;
    const int tg  = lane & 3;
#pragma unroll
    for (int im = 0; im < 4; im++) {
        const int r0 = m0 + wm + im * 16 + gid;
        const int r1 = r0 + 8;
#pragma unroll
        for (int in = 0; in < 4; in++) {
            const int col = n0 + wn + in * 8 + tg * 2;
            *(float2*)(S + (size_t)r0 * CAP + col) = make_float2(acc[im][in][0], acc[im][in][1]);
            *(float2*)(S + (size_t)r1 * CAP + col) = make_float2(acc[im][in][2], acc[im][in][3]);
        }
    }
}

// ---------------------------------------------------------------------------
// Softmax over valid keys; P normalized, bf16 hi/lo. Grid (64, 8), warp/row.
// ---------------------------------------------------------------------------
__global__ __launch_bounds__(256) void softmax_kernel()
{
    const int g  = blockIdx.x;
    const int rb = blockIdx.y;       // 32 rows per CTA
    const int n  = g_cnt[g];
    const int np = (n + 63) & ~63;
    const int warp = threadIdx.x >> 5;
    const int lane = threadIdx.x & 31;
    const float scale = 0.04419417382415922f;   // 1/sqrt(512)

    for (int rr = 0; rr < 4; rr++) {
        const int r = rb * 32 + rr * 8 + warp;
        if (r >= n) continue;
        const float* srow = g_S[g] + (size_t)r * CAP;
        float s[8];
        float mx = -INFINITY;
#pragma unroll
        for (int j = 0; j < 8; j++) {
            int k = lane + 32 * j;
            s[j] = (k < n) ? srow[k] * scale : -INFINITY;
            mx = fmaxf(mx, s[j]);
        }
#pragma unroll
        for (int off = 16; off > 0; off >>= 1)
            mx = fmaxf(mx, __shfl_xor_sync(0xffffffffu, mx, off));
        float sum = 0.f;
#pragma unroll
        for (int j = 0; j < 8; j++) {
            s[j] = (lane + 32 * j < n) ? __expf(s[j] - mx) : 0.f;
            sum += s[j];
        }
#pragma unroll
        for (int off = 16; off > 0; off >>= 1)
            sum += __shfl_xor_sync(0xffffffffu, sum, off);
        const float inv = 1.0f / sum;
#pragma unroll
        for (int j = 0; j < 8; j++) {
            int k = lane + 32 * j;
            if (k < np) {
                float p = s[j] * inv;   // 0 for k in [n, np)
                __nv_bfloat16 h = __float2bfloat16_rn(p);
                float res = p - __bfloat162float(h);
                g_Phi[g][(size_t)r * CAP + k] = h;
                g_Plo[g][(size_t)r * CAP + k] = __float2bfloat16_rn(res);
            }
        }
    }
}

// ---------------------------------------------------------------------------
// PV GEMM: O_g = P_g @ V_g (A=P stride CAP, B=VT stride CAP), scatter rows.
// Grid (64, 4, 2). Runtime K chunks = ceil(n/64).
// ---------------------------------------------------------------------------
__global__ __launch_bounds__(256) void pv_mma_kernel(float* __restrict__ Aout)
{
    const int g  = blockIdx.x;
    const int n  = g_cnt[g];
    const int n0 = blockIdx.y * 128;   // dim tile
    const int m0 = blockIdx.z * 128;   // query tile
    if (m0 >= n) return;
    const int nch = ((n + 63) & ~63) >> 6;   // 1..4

    extern __shared__ char smem_c[];
    __shared__ int rO[128];
    const uint32_t sb = smem_to_u32(smem_c);
    const int tid  = threadIdx.x;
    const int wid  = tid >> 5;
    const int lane = tid & 31;
    const int wm = (wid & 1) * 64;
    const int wn = (wid >> 1) * 32;

    if (tid < 128) rO[tid] = g_list[g][m0 + tid];
    __syncthreads();

    const char* Phi = (const char*)g_Phi[g];
    const char* Plo = (const char*)g_Plo[g];
    const char* VTh = (const char*)g_VThi[g];
    const char* VTl = (const char*)g_VTlo[g];

    float acc[4][4][4];
#pragma unroll
    for (int im = 0; im < 4; im++)
#pragma unroll
        for (int in = 0; in < 4; in++)
#pragma unroll
            for (int e = 0; e < 4; e++) acc[im][in][e] = 0.f;

    load_tile2(sb + 0 * TILE_BYTES, Phi, CAP * 2, m0, 0, tid);
    load_tile2(sb + 1 * TILE_BYTES, Plo, CAP * 2, m0, 0, tid);
    load_tile2(sb + 2 * TILE_BYTES, VTh, CAP * 2, n0, 0, tid);
    load_tile2(sb + 3 * TILE_BYTES, VTl, CAP * 2, n0, 0, tid);
    cp_commit();

    const int rowA  = wm + (lane & 15);
    const int rowB  = wn + (lane & 15);
    const int khalf = (lane >> 4) * 8;

    for (int kc = 0; kc < nch; kc++) {
        const uint32_t cur = sb + (uint32_t)(kc & 1) * STAGE_B;
        if (kc + 1 < nch) {
            uint32_t nxt = sb + (uint32_t)((kc + 1) & 1) * STAGE_B;
            load_tile2(nxt + 0 * TILE_BYTES, Phi, CAP * 2, m0, kc + 1, tid);
            load_tile2(nxt + 1 * TILE_BYTES, Plo, CAP * 2, m0, kc + 1, tid);
            load_tile2(nxt + 2 * TILE_BYTES, VTh, CAP * 2, n0, kc + 1, tid);
            load_tile2(nxt + 3 * TILE_BYTES, VTl, CAP * 2, n0, kc + 1, tid);
            cp_commit();
            cp_wait1();
        } else {
            cp_wait0();
        }
        __syncthreads();
        mma_chunk(cur, rowA, rowB, khalf, acc);
        __syncthreads();
    }

    const int gid = lane >> 2;
    const int tg  = lane & 3;
#pragma unroll
    for (int im = 0; im < 4; im++) {
        const int lr0 = wm + im * 16 + gid;
        const int lr1 = lr0 + 8;
#pragma unroll
        for (int in = 0; in < 4; in++) {
            const int col = n0 + wn + in * 8 + tg * 2;
            if (m0 + lr0 < n)
                *(float2*)(Aout + (size_t)rO[lr0] * 512 + col) = make_float2(acc[im][in][0], acc[im][in][1]);
            if (m0 + lr1 < n)
                *(float2*)(Aout + (size_t)rO[lr1] * 512 + col) = make_float2(acc[im][in][2], acc[im][in][3]);
        }
    }
}

// ---------------------------------------------------------------------------
// Zero rows with label == -1.
// ---------------------------------------------------------------------------
__global__ __launch_bounds__(128) void zero_invalid_kernel(
    const int* __restrict__ labels, float* __restrict__ A)
{
    const int row = blockIdx.x;
    if (labels[row] >= 0) return;
    ((float4*)(A + (size_t)row * 512))[threadIdx.x] = make_float4(0.f, 0.f, 0.f, 0.f);
}

// ---------------------------------------------------------------------------
extern "C" void kernel_launch(void* const* d_in, const int* in_sizes, int n_in,
                              void* d_out, int out_size)
{
    const float* x      = (const float*)d_in[0];
    const int*   labels = (const int*)  d_in[1];
    const float* Wq     = (const float*)d_in[2];
    const float* bq     = (const float*)d_in[3];
    const float* Wk     = (const float*)d_in[4];
    const float* bk     = (const float*)d_in[5];
    const float* Wv     = (const float*)d_in[6];
    const float* bv     = (const float*)d_in[7];
    const float* Wo     = (const float*)d_in[8];
    const float* bo     = (const float*)d_in[9];
    float* out = (float*)d_out;

    float *Qp, *Kp, *Vp, *Ap;
    cudaGetSymbolAddress((void**)&Qp, g_Q);
    cudaGetSymbolAddress((void**)&Kp, g_K);
    cudaGetSymbolAddress((void**)&Vp, g_V);
    cudaGetSymbolAddress((void**)&Ap, g_A);
    __nv_bfloat16 *xhi, *xlo, *ahi, *alo, *khi, *klo, *whi, *wlo;
    cudaGetSymbolAddress((void**)&xhi, g_xhi);
    cudaGetSymbolAddress((void**)&xlo, g_xlo);
    cudaGetSymbolAddress((void**)&ahi, g_ahi);
    cudaGetSymbolAddress((void**)&alo, g_alo);
    cudaGetSymbolAddress((void**)&khi, g_khi);
    cudaGetSymbolAddress((void**)&klo, g_klo);
    cudaGetSymbolAddress((void**)&whi, g_whi);
    cudaGetSymbolAddress((void**)&wlo, g_wlo);

    cudaFuncSetAttribute(gemm_mma_kernel,   cudaFuncAttributeMaxDynamicSharedMemorySize, GEMM_SMEM_TOTAL);
    cudaFuncSetAttribute(scores_mma_kernel, cudaFuncAttributeMaxDynamicSharedMemorySize, GEMM_SMEM_TOTAL);
    cudaFuncSetAttribute(pv_mma_kernel,     cudaFuncAttributeMaxDynamicSharedMemorySize, GEMM_SMEM_TOTAL);

    const int nelem = NROWS * DIM;
    split_kernel<<<(nelem + 255) / 256, 256>>>(x, xhi, xlo, nelem);

    dim3 wgrid(16, 16);
    wsplit_t_kernel<<<wgrid, 256>>>(Wq, whi + 0 * DIM * DIM, wlo + 0 * DIM * DIM);
    wsplit_t_kernel<<<wgrid, 256>>>(Wk, whi + 1 * DIM * DIM, wlo + 1 * DIM * DIM);
    wsplit_t_kernel<<<wgrid, 256>>>(Wv, whi + 2 * DIM * DIM, wlo + 2 * DIM * DIM);
    wsplit_t_kernel<<<wgrid, 256>>>(Wo, whi + 3 * DIM * DIM, wlo + 3 * DIM * DIM);

    dim3 ggrid(DIM / 128, NROWS / 128);   // (4, 64)
    gemm_mma_kernel<<<ggrid, 256, GEMM_SMEM_TOTAL>>>(xhi, xlo, whi + 0 * DIM * DIM, wlo + 0 * DIM * DIM, bq, Qp);
    gemm_mma_kernel<<<ggrid, 256, GEMM_SMEM_TOTAL>>>(xhi, xlo, whi + 1 * DIM * DIM, wlo + 1 * DIM * DIM, bk, Kp);
    gemm_mma_kernel<<<ggrid, 256, GEMM_SMEM_TOTAL>>>(xhi, xlo, whi + 2 * DIM * DIM, wlo + 2 * DIM * DIM, bv, Vp);

    build_lists_kernel<<<NG, 256>>>(labels);
    split_kernel<<<(nelem + 255) / 256, 256>>>(Qp, ahi, alo, nelem);   // Q hi/lo (ahi reused)
    split_kernel<<<(nelem + 255) / 256, 256>>>(Kp, khi, klo, nelem);
    vt_build_kernel<<<dim3(NG, CAP / 32), 256>>>(Vp);

    scores_mma_kernel<<<dim3(NG, 2, 2), 256, GEMM_SMEM_TOTAL>>>(ahi, alo, khi, klo);
    softmax_kernel<<<dim3(NG, CAP / 32), 256>>>();
    zero_invalid_kernel<<<NROWS, 128>>>(labels, Ap);
    pv_mma_kernel<<<dim3(NG, 4, 2), 256, GEMM_SMEM_TOTAL>>>(Ap);

    split_kernel<<<(nelem + 255) / 256, 256>>>(Ap, ahi, alo, nelem);   // A hi/lo (reuse)
    gemm_mma_kernel<<<ggrid, 256, GEMM_SMEM_TOTAL>>>(ahi, alo, whi + 3 * DIM * DIM, wlo + 3 * DIM * DIM, bo, out);
}

// round 12
// speedup vs baseline: 1.7958x; 1.5423x over previous
#include <cuda_runtime.h>
#include <cuda_fp16.h>
#include <math.h>
#include <stdint.h>

#define NROWS 8192
#define DIM   512
#define NG    64
#define CAP   256

// ---------------------------------------------------------------------------
// Scratch (static device globals — zero-initialized, no runtime allocation).
// ---------------------------------------------------------------------------
__device__ __half g_xh [NROWS * DIM];          // x fp16
__device__ __half g_qh [NROWS * DIM];          // Q fp16
__device__ __half g_khi[NROWS * DIM];          // K hi/lo fp16
__device__ __half g_klo[NROWS * DIM];
__device__ float  g_V  [NROWS * DIM];          // V fp32 (for VT build)
__device__ __half g_ah [NROWS * DIM];          // attention output fp16
__device__ __half g_whi[4][DIM * DIM];         // W^T hi/lo fp16 [N][K]
__device__ __half g_wlo[4][DIM * DIM];

__device__ int    g_list[NG][CAP];
__device__ int    g_cnt[NG];
__device__ float  g_S  [NG][CAP * CAP];        // scaled scores fp32
__device__ __half g_Ph [NG][CAP * CAP];        // softmax probs fp16
__device__ __half g_VThi[NG][DIM * CAP];       // V^T hi/lo fp16 [dim][key]
__device__ __half g_VTlo[NG][DIM * CAP];

// ---------------------------------------------------------------------------
// Helpers (baseline sm_103 ISA)
// ---------------------------------------------------------------------------
__device__ __forceinline__ uint32_t smem_to_u32(const void* p) {
    uint32_t a;
    asm("{ .reg .u64 t; cvta.to.shared.u64 t, %1; cvt.u32.u64 %0, t; }" : "=r"(a) : "l"(p));
    return a;
}
__device__ __forceinline__ void cp_async16(uint32_t s, const void* g) {
    asm volatile("cp.async.cg.shared.global [%0], [%1], 16;" :: "r"(s), "l"(g));
}
__device__ __forceinline__ void cp_commit() { asm volatile("cp.async.commit_group;" ::: "memory"); }
__device__ __forceinline__ void cp_wait1()  { asm volatile("cp.async.wait_group 1;" ::: "memory"); }
__device__ __forceinline__ void cp_wait0()  { asm volatile("cp.async.wait_group 0;" ::: "memory"); }

__device__ __forceinline__ void ldsm_x4(uint32_t* r, uint32_t addr) {
    asm volatile("ldmatrix.sync.aligned.m8n8.x4.shared.b16 {%0,%1,%2,%3}, [%4];"
                 : "=r"(r[0]), "=r"(r[1]), "=r"(r[2]), "=r"(r[3]) : "r"(addr));
}
__device__ __forceinline__ void mma16816(float* d, const uint32_t* a, uint32_t b0, uint32_t b1) {
    asm volatile(
        "mma.sync.aligned.m16n8k16.row.col.f32.f16.f16.f32 "
        "{%0,%1,%2,%3}, {%4,%5,%6,%7}, {%8,%9}, {%0,%1,%2,%3};"
        : "+f"(d[0]), "+f"(d[1]), "+f"(d[2]), "+f"(d[3])
        : "r"(a[0]), "r"(a[1]), "r"(a[2]), "r"(a[3]), "r"(b0), "r"(b1));
}

// ---------------------------------------------------------------------------
// Shared HMMA core: A single fp16, B = hi + lo fp16 (2-term).
// Stage = 3 tiles (A, Bh, Bl) of 128 rows x 64 halves, row stride 144 B.
// ---------------------------------------------------------------------------
static constexpr int TILE_BYTES = 128 * 144;           // 18432
static constexpr int STAGE3     = 3 * TILE_BYTES;      // 55296
static constexpr int SMEM3      = 2 * STAGE3;          // 110592

__device__ __forceinline__ void load_tile2(
    uint32_t sdst, const char* src, size_t stride_b, int rowbase, int kc, int tid)
{
#pragma unroll
    for (int i = 0; i < 4; i++) {
        int f   = tid + i * 256;
        int row = f >> 3;
        int c   = f & 7;
        cp_async16(sdst + row * 144 + c * 16,
                   src + (size_t)(rowbase + row) * stride_b + (size_t)kc * 128 + c * 16);
    }
}
__device__ __forceinline__ void load_tile_idx(
    uint32_t sdst, const char* src, const int* rows, int kc, int tid)
{
#pragma unroll
    for (int i = 0; i < 4; i++) {
        int f   = tid + i * 256;
        int row = f >> 3;
        int c   = f & 7;
        cp_async16(sdst + row * 144 + c * 16,
                   src + (size_t)rows[row] * 1024 + (size_t)kc * 128 + c * 16);
    }
}

__device__ __forceinline__ void mma_chunk2(
    uint32_t cur, int rowA, int rowB, int khalf, float acc[4][4][4])
{
    const uint32_t sA  = cur;
    const uint32_t sBh = cur + TILE_BYTES;
    const uint32_t sBl = cur + 2 * TILE_BYTES;
#pragma unroll
    for (int ks = 0; ks < 4; ks++) {
        const int ke = ks * 16 + khalf;
        uint32_t a[4][4], bh[2][4], bl[2][4];
#pragma unroll
        for (int im = 0; im < 4; im++)
            ldsm_x4(a[im], sA + ((rowA + im * 16) * 72 + ke) * 2);
#pragma unroll
        for (int ib = 0; ib < 2; ib++) {
            ldsm_x4(bh[ib], sBh + ((rowB + ib * 16) * 72 + ke) * 2);
            ldsm_x4(bl[ib], sBl + ((rowB + ib * 16) * 72 + ke) * 2);
        }
#pragma unroll
        for (int im = 0; im < 4; im++) {
#pragma unroll
            for (int in = 0; in < 4; in++) {
                const int ib  = in >> 1;
                const int sel = in & 1;
                mma16816(acc[im][in], a[im], bh[ib][sel], bh[ib][sel + 2]);
                mma16816(acc[im][in], a[im], bl[ib][sel], bl[ib][sel + 2]);
            }
        }
    }
}

#define GEMM_PROLOG() \
    extern __shared__ char smem_c[]; \
    const uint32_t sb = smem_to_u32(smem_c); \
    const int tid  = threadIdx.x; \
    const int wid  = tid >> 5; \
    const int lane = tid & 31; \
    const int wm = (wid & 1) * 64; \
    const int wn = (wid >> 1) * 32; \
    const int rowA  = wm + (lane & 15); \
    const int rowB  = wn + (lane & 15); \
    const int khalf = (lane >> 4) * 8; \
    float acc[4][4][4]; \
    _Pragma("unroll") for (int im = 0; im < 4; im++) \
    _Pragma("unroll") for (int in = 0; in < 4; in++) \
    _Pragma("unroll") for (int e = 0; e < 4; e++) acc[im][in][e] = 0.f;

// ---------------------------------------------------------------------------
// fp32 -> fp16 (elementwise)
// ---------------------------------------------------------------------------
__global__ __launch_bounds__(256) void tohalf_kernel(const float* __restrict__ x, int n)
{
    int i = blockIdx.x * 256 + threadIdx.x;
    if (i < n) g_xh[i] = __float2half_rn(x[i]);
}

// ---------------------------------------------------------------------------
// All 4 weights: [K][N] -> transposed fp16 hi/lo [N][K]. Grid (16,16,4).
// ---------------------------------------------------------------------------
__global__ __launch_bounds__(256) void wsplit4_kernel(
    const float* __restrict__ W0, const float* __restrict__ W1,
    const float* __restrict__ W2, const float* __restrict__ W3)
{
    const int z = blockIdx.z;
    const float* W = (z == 0) ? W0 : (z == 1) ? W1 : (z == 2) ? W2 : W3;
    __shared__ float t[32][33];
    const int tx = threadIdx.x & 31;
    const int ty = threadIdx.x >> 5;
    const int k0 = blockIdx.y * 32;
    const int n0 = blockIdx.x * 32;
#pragma unroll
    for (int i = 0; i < 32; i += 8)
        t[ty + i][tx] = W[(size_t)(k0 + ty + i) * 512 + n0 + tx];
    __syncthreads();
#pragma unroll
    for (int i = 0; i < 32; i += 8) {
        float v = t[tx][ty + i];
        __half h = __float2half_rn(v);
        float r = v - __half2float(h);
        size_t idx = (size_t)(n0 + ty + i) * 512 + k0 + tx;
        g_whi[z][idx] = h;
        g_wlo[z][idx] = __float2half_rn(r);
    }
}

// ---------------------------------------------------------------------------
// Fused QKV projection. Grid (4, 64, 3). z: 0=Q(fp16), 1=K(hi/lo), 2=V(fp32).
// ---------------------------------------------------------------------------
__global__ __launch_bounds__(256) void qkv_kernel(
    const float* __restrict__ bq, const float* __restrict__ bk, const float* __restrict__ bv)
{
    const int z  = blockIdx.z;
    const int m0 = blockIdx.y * 128;
    const int n0 = blockIdx.x * 128;
    const float* bias = (z == 0) ? bq : (z == 1) ? bk : bv;
    const char* A  = (const char*)g_xh;
    const char* Bh = (const char*)g_whi[z];
    const char* Bl = (const char*)g_wlo[z];

    GEMM_PROLOG();

    load_tile2(sb + 0 * TILE_BYTES, A,  1024, m0, 0, tid);
    load_tile2(sb + 1 * TILE_BYTES, Bh, 1024, n0, 0, tid);
    load_tile2(sb + 2 * TILE_BYTES, Bl, 1024, n0, 0, tid);
    cp_commit();

    for (int kc = 0; kc < 8; kc++) {
        const uint32_t cur = sb + (uint32_t)(kc & 1) * STAGE3;
        if (kc < 7) {
            uint32_t nxt = sb + (uint32_t)((kc + 1) & 1) * STAGE3;
            load_tile2(nxt + 0 * TILE_BYTES, A,  1024, m0, kc + 1, tid);
            load_tile2(nxt + 1 * TILE_BYTES, Bh, 1024, n0, kc + 1, tid);
            load_tile2(nxt + 2 * TILE_BYTES, Bl, 1024, n0, kc + 1, tid);
            cp_commit();
            cp_wait1();
        } else {
            cp_wait0();
        }
        __syncthreads();
        mma_chunk2(cur, rowA, rowB, khalf, acc);
        __syncthreads();
    }

    const int gid = lane >> 2;
    const int tg  = lane & 3;
#pragma unroll
    for (int im = 0; im < 4; im++) {
#pragma unroll
        for (int half = 0; half < 2; half++) {
            const int r = m0 + wm + im * 16 + gid + half * 8;
#pragma unroll
            for (int in = 0; in < 4; in++) {
                const int col = n0 + wn + in * 8 + tg * 2;
                float v0 = acc[im][in][half * 2 + 0] + bias[col];
                float v1 = acc[im][in][half * 2 + 1] + bias[col + 1];
                if (z == 0) {
                    *(__half2*)&g_qh[(size_t)r * 512 + col] = __floats2half2_rn(v0, v1);
                } else if (z == 1) {
                    __half h0 = __float2half_rn(v0), h1 = __float2half_rn(v1);
                    *(__half2*)&g_khi[(size_t)r * 512 + col] = __halves2half2(h0, h1);
                    *(__half2*)&g_klo[(size_t)r * 512 + col] =
                        __floats2half2_rn(v0 - __half2float(h0), v1 - __half2float(h1));
                } else {
                    *(float2*)&g_V[(size_t)r * 512 + col] = make_float2(v0, v1);
                }
            }
        }
    }
}

// ---------------------------------------------------------------------------
// Output projection: out = ah @ Wo^T + bo (fp32). Grid (4, 64).
// ---------------------------------------------------------------------------
__global__ __launch_bounds__(256) void out_gemm_kernel(
    const float* __restrict__ bias, float* __restrict__ C)
{
    const int m0 = blockIdx.y * 128;
    const int n0 = blockIdx.x * 128;
    const char* A  = (const char*)g_ah;
    const char* Bh = (const char*)g_whi[3];
    const char* Bl = (const char*)g_wlo[3];

    GEMM_PROLOG();

    load_tile2(sb + 0 * TILE_BYTES, A,  1024, m0, 0, tid);
    load_tile2(sb + 1 * TILE_BYTES, Bh, 1024, n0, 0, tid);
    load_tile2(sb + 2 * TILE_BYTES, Bl, 1024, n0, 0, tid);
    cp_commit();

    for (int kc = 0; kc < 8; kc++) {
        const uint32_t cur = sb + (uint32_t)(kc & 1) * STAGE3;
        if (kc < 7) {
            uint32_t nxt = sb + (uint32_t)((kc + 1) & 1) * STAGE3;
            load_tile2(nxt + 0 * TILE_BYTES, A,  1024, m0, kc + 1, tid);
            load_tile2(nxt + 1 * TILE_BYTES, Bh, 1024, n0, kc + 1, tid);
            load_tile2(nxt + 2 * TILE_BYTES, Bl, 1024, n0, kc + 1, tid);
            cp_commit();
            cp_wait1();
        } else {
            cp_wait0();
        }
        __syncthreads();
        mma_chunk2(cur, rowA, rowB, khalf, acc);
        __syncthreads();
    }

    const int gid = lane >> 2;
    const int tg  = lane & 3;
#pragma unroll
    for (int im = 0; im < 4; im++) {
        const int r0 = m0 + wm + im * 16 + gid;
        const int r1 = r0 + 8;
#pragma unroll
        for (int in = 0; in < 4; in++) {
            const int col = n0 + wn + in * 8 + tg * 2;
            const float b0 = bias[col], b1 = bias[col + 1];
            *(float2*)(C + (size_t)r0 * 512 + col) = make_float2(acc[im][in][0] + b0, acc[im][in][1] + b1);
            *(float2*)(C + (size_t)r1 * 512 + col) = make_float2(acc[im][in][2] + b0, acc[im][in][3] + b1);
        }
    }
}

// ---------------------------------------------------------------------------
// Build per-group row lists (deterministic ascending). Grid = 64.
// ---------------------------------------------------------------------------
__global__ __launch_bounds__(256) void build_lists_kernel(const int* __restrict__ labels)
{
    __shared__ int s_cnt[256], s_pre[256], s_list[512];
    const int g    = blockIdx.x;
    const int tid  = threadIdx.x;
    const int warp = tid >> 5;
    const int lane = tid & 31;

    for (int c = warp; c < 256; c += 8) {
        int lab = labels[c * 32 + lane];
        unsigned m = __ballot_sync(0xffffffffu, lab == g);
        if (lane == 0) s_cnt[c] = __popc(m);
    }
    __syncthreads();
    if (warp == 0) {
        int vals[8];
        int run = 0;
#pragma unroll
        for (int j = 0; j < 8; j++) { int t = s_cnt[lane * 8 + j]; vals[j] = run; run += t; }
        int x = run;
#pragma unroll
        for (int off = 1; off < 32; off <<= 1) {
            int y = __shfl_up_sync(0xffffffffu, x, off);
            if (lane >= off) x += y;
        }
        int excl = x - run;
#pragma unroll
        for (int j = 0; j < 8; j++) s_pre[lane * 8 + j] = excl + vals[j];
    }
    __syncthreads();
    const int n = s_pre[255] + s_cnt[255];
    for (int c = warp; c < 256; c += 8) {
        int lab = labels[c * 32 + lane];
        unsigned m = __ballot_sync(0xffffffffu, lab == g);
        if (lab == g) {
            int idx = s_pre[c] + __popc(m & ((1u << lane) - 1));
            if (idx < 512) s_list[idx] = c * 32 + lane;
        }
    }
    __syncthreads();
    if (tid < CAP) g_list[g][tid] = (tid < n) ? s_list[tid] : 0;
    if (tid == 0) g_cnt[g] = (n > CAP) ? CAP : n;
}

// ---------------------------------------------------------------------------
// Gather + transpose + split V -> VT[g][dim][key] fp16 hi/lo. Grid (64, 8).
// ---------------------------------------------------------------------------
__global__ __launch_bounds__(256) void vt_build_kernel()
{
    const int g  = blockIdx.x;
    const int kt = blockIdx.y;
    const int n  = g_cnt[g];
    if (kt * 32 >= n) return;

    __shared__ float t[32][33];
    __shared__ int rows[32];
    const int tx = threadIdx.x & 31;
    const int ty = threadIdx.x >> 5;
    if (threadIdx.x < 32) {
        int key = kt * 32 + threadIdx.x;
        rows[threadIdx.x] = (key < n) ? g_list[g][key] : -1;
    }
    __syncthreads();

    for (int db = 0; db < 16; db++) {
#pragma unroll
        for (int i = 0; i < 32; i += 8) {
            int r = rows[ty + i];
            t[ty + i][tx] = (r >= 0) ? g_V[(size_t)r * 512 + db * 32 + tx] : 0.f;
        }
        __syncthreads();
#pragma unroll
        for (int i = 0; i < 32; i += 8) {
            int d = db * 32 + ty + i;
            int k = kt * 32 + tx;
            if (k < n) {
                float v = t[tx][ty + i];
                __half h = __float2half_rn(v);
                g_VThi[g][d * CAP + k] = h;
                g_VTlo[g][d * CAP + k] = __float2half_rn(v - __half2float(h));
            }
        }
        __syncthreads();
    }
}

// ---------------------------------------------------------------------------
// Scores: S_g = scale * Qh_g @ (Khi+Klo)_g^T. Grid (64,2,2), indirect rows.
// ---------------------------------------------------------------------------
__global__ __launch_bounds__(256) void scores_mma_kernel()
{
    const int g  = blockIdx.x;
    const int n  = g_cnt[g];
    const int n0 = blockIdx.y * 128;
    const int m0 = blockIdx.z * 128;
    if (m0 >= n || n0 >= n) return;

    __shared__ int rA[128], rB[128];
    GEMM_PROLOG();

    if (tid < 128) rA[tid] = g_list[g][m0 + tid];
    else           rB[tid - 128] = g_list[g][n0 + tid - 128];
    __syncthreads();

    load_tile_idx(sb + 0 * TILE_BYTES, (const char*)g_qh,  rA, 0, tid);
    load_tile_idx(sb + 1 * TILE_BYTES, (const char*)g_khi, rB, 0, tid);
    load_tile_idx(sb + 2 * TILE_BYTES, (const char*)g_klo, rB, 0, tid);
    cp_commit();

    for (int kc = 0; kc < 8; kc++) {
        const uint32_t cur = sb + (uint32_t)(kc & 1) * STAGE3;
        if (kc < 7) {
            uint32_t nxt = sb + (uint32_t)((kc + 1) & 1) * STAGE3;
            load_tile_idx(nxt + 0 * TILE_BYTES, (const char*)g_qh,  rA, kc + 1, tid);
            load_tile_idx(nxt + 1 * TILE_BYTES, (const char*)g_khi, rB, kc + 1, tid);
            load_tile_idx(nxt + 2 * TILE_BYTES, (const char*)g_klo, rB, kc + 1, tid);
            cp_commit();
            cp_wait1();
        } else {
            cp_wait0();
        }
        __syncthreads();
        mma_chunk2(cur, rowA, rowB, khalf, acc);
        __syncthreads();
    }

    const float scale = 0.04419417382415922f;  // 1/sqrt(512)
    float* S = g_S[g];
    const int gid = lane >> 2;
    const int tg  = lane & 3;
#pragma unroll
    for (int im = 0; im < 4; im++) {
        const int r0 = m0 + wm + im * 16 + gid;
        const int r1 = r0 + 8;
#pragma unroll
        for (int in = 0; in < 4; in++) {
            const int col = n0 + wn + in * 8 + tg * 2;
            *(float2*)(S + (size_t)r0 * CAP + col) =
                make_float2(acc[im][in][0] * scale, acc[im][in][1] * scale);
            *(float2*)(S + (size_t)r1 * CAP + col) =
                make_float2(acc[im][in][2] * scale, acc[im][in][3] * scale);
        }
    }
}

// ---------------------------------------------------------------------------
// Softmax over valid keys -> P fp16 (zero-padded to 64-multiple). Grid (64,8).
// ---------------------------------------------------------------------------
__global__ __launch_bounds__(256) void softmax_kernel()
{
    const int g  = blockIdx.x;
    const int rb = blockIdx.y;
    const int n  = g_cnt[g];
    const int np = (n + 63) & ~63;
    const int warp = threadIdx.x >> 5;
    const int lane = threadIdx.x & 31;

    for (int rr = 0; rr < 4; rr++) {
        const int r = rb * 32 + rr * 8 + warp;
        if (r >= n) continue;
        const float* srow = g_S[g] + (size_t)r * CAP;
        float s[8];
        float mx = -INFINITY;
#pragma unroll
        for (int j = 0; j < 8; j++) {
            int k = lane + 32 * j;
            s[j] = (k < n) ? srow[k] : -INFINITY;
            mx = fmaxf(mx, s[j]);
        }
#pragma unroll
        for (int off = 16; off > 0; off >>= 1)
            mx = fmaxf(mx, __shfl_xor_sync(0xffffffffu, mx, off));
        float sum = 0.f;
#pragma unroll
        for (int j = 0; j < 8; j++) {
            s[j] = (lane + 32 * j < n) ? __expf(s[j] - mx) : 0.f;
            sum += s[j];
        }
#pragma unroll
        for (int off = 16; off > 0; off >>= 1)
            sum += __shfl_xor_sync(0xffffffffu, sum, off);
        const float inv = 1.0f / sum;
#pragma unroll
        for (int j = 0; j < 8; j++) {
            int k = lane + 32 * j;
            if (k < np) g_Ph[g][(size_t)r * CAP + k] = __float2half_rn(s[j] * inv);
        }
    }
}

// ---------------------------------------------------------------------------
// PV: O_g = P_g @ V_g -> scatter fp16 rows into g_ah. Grid (64, 4, 2).
// ---------------------------------------------------------------------------
__global__ __launch_bounds__(256) void pv_mma_kernel()
{
    const int g  = blockIdx.x;
    const int n  = g_cnt[g];
    const int n0 = blockIdx.y * 128;   // dim tile
    const int m0 = blockIdx.z * 128;   // query tile
    if (m0 >= n) return;
    const int nch = ((n + 63) & ~63) >> 6;

    __shared__ int rO[128];
    GEMM_PROLOG();

    if (tid < 128) rO[tid] = g_list[g][m0 + tid];
    __syncthreads();

    const char* P   = (const char*)g_Ph[g];
    const char* VTh = (const char*)g_VThi[g];
    const char* VTl = (const char*)g_VTlo[g];

    load_tile2(sb + 0 * TILE_BYTES, P,   CAP * 2, m0, 0, tid);
    load_tile2(sb + 1 * TILE_BYTES, VTh, CAP * 2, n0, 0, tid);
    load_tile2(sb + 2 * TILE_BYTES, VTl, CAP * 2, n0, 0, tid);
    cp_commit();

    for (int kc = 0; kc < nch; kc++) {
        const uint32_t cur = sb + (uint32_t)(kc & 1) * STAGE3;
        if (kc + 1 < nch) {
            uint32_t nxt = sb + (uint32_t)((kc + 1) & 1) * STAGE3;
            load_tile2(nxt + 0 * TILE_BYTES, P,   CAP * 2, m0, kc + 1, tid);
            load_tile2(nxt + 1 * TILE_BYTES, VTh, CAP * 2, n0, kc + 1, tid);
            load_tile2(nxt + 2 * TILE_BYTES, VTl, CAP * 2, n0, kc + 1, tid);
            cp_commit();
            cp_wait1();
        } else {
            cp_wait0();
        }
        __syncthreads();
        mma_chunk2(cur, rowA, rowB, khalf, acc);
        __syncthreads();
    }

    const int gid = lane >> 2;
    const int tg  = lane & 3;
#pragma unroll
    for (int im = 0; im < 4; im++) {
        const int lr0 = wm + im * 16 + gid;
        const int lr1 = lr0 + 8;
#pragma unroll
        for (int in = 0; in < 4; in++) {
            const int col = n0 + wn + in * 8 + tg * 2;
            if (m0 + lr0 < n)
                *(__half2*)&g_ah[(size_t)rO[lr0] * 512 + col] =
                    __floats2half2_rn(acc[im][in][0], acc[im][in][1]);
            if (m0 + lr1 < n)
                *(__half2*)&g_ah[(size_t)rO[lr1] * 512 + col] =
                    __floats2half2_rn(acc[im][in][2], acc[im][in][3]);
        }
    }
}

// ---------------------------------------------------------------------------
// Zero ah rows with label == -1.
// ---------------------------------------------------------------------------
__global__ __launch_bounds__(64) void zero_invalid_kernel(const int* __restrict__ labels)
{
    const int row = blockIdx.x;
    if (labels[row] >= 0) return;
    ((uint4*)(g_ah + (size_t)row * 512))[threadIdx.x] = make_uint4(0, 0, 0, 0);
}

// ---------------------------------------------------------------------------
extern "C" void kernel_launch(void* const* d_in, const int* in_sizes, int n_in,
                              void* d_out, int out_size)
{
    const float* x      = (const float*)d_in[0];
    const int*   labels = (const int*)  d_in[1];
    const float* Wq     = (const float*)d_in[2];
    const float* bq     = (const float*)d_in[3];
    const float* Wk     = (const float*)d_in[4];
    const float* bk     = (const float*)d_in[5];
    const float* Wv     = (const float*)d_in[6];
    const float* bv     = (const float*)d_in[7];
    const float* Wo     = (const float*)d_in[8];
    const float* bo     = (const float*)d_in[9];
    float* out = (float*)d_out;

    cudaFuncSetAttribute(qkv_kernel,        cudaFuncAttributeMaxDynamicSharedMemorySize, SMEM3);
    cudaFuncSetAttribute(out_gemm_kernel,   cudaFuncAttributeMaxDynamicSharedMemorySize, SMEM3);
    cudaFuncSetAttribute(scores_mma_kernel, cudaFuncAttributeMaxDynamicSharedMemorySize, SMEM3);
    cudaFuncSetAttribute(pv_mma_kernel,     cudaFuncAttributeMaxDynamicSharedMemorySize, SMEM3);

    const int nelem = NROWS * DIM;
    tohalf_kernel<<<nelem / 256, 256>>>(x, nelem);
    wsplit4_kernel<<<dim3(16, 16, 4), 256>>>(Wq, Wk, Wv, Wo);
    build_lists_kernel<<<NG, 256>>>(labels);

    qkv_kernel<<<dim3(4, 64, 3), 256, SMEM3>>>(bq, bk, bv);

    vt_build_kernel<<<dim3(NG, CAP / 32), 256>>>();
    scores_mma_kernel<<<dim3(NG, 2, 2), 256, SMEM3>>>();
    softmax_kernel<<<dim3(NG, CAP / 32), 256>>>();
    pv_mma_kernel<<<dim3(NG, 4, 2), 256, SMEM3>>>();
    zero_invalid_kernel<<<NROWS, 64>>>(labels);

    out_gemm_kernel<<<dim3(4, 64), 256, SMEM3>>>(bo, out);
}